// round 16
// baseline (speedup 1.0000x reference)
#include <cuda_runtime.h>
#include <cuda_fp8.h>
#include <cstdint>

#define BATCH 2048
#define VOCAB 50000
#define EMB   100
#define CTX   10
#define KPF   128          // K padded to 128 fp8 (4 x k32 mma steps)
#define VP    50176        // 784 * 64
#define NT    784          // number of 64-row B tiles
#define BM    128
#define BN    64
#define NSLICE 27
#define NCTA  (NSLICE * 16)   // 432 CTAs, all co-resident at 3 CTAs/SM
#define STRB   144            // smem row stride bytes (128B data + 16 pad)
#define ABYTES (BM * STRB) // 18432
#define BBYTES (BN * STRB) // 9216
#define SMEM_TOTAL (ABYTES + 2 * BBYTES)  // 36864

// Scratch (device globals, zero-init at module load)
__device__ __align__(16) char    g_hq[BATCH * KPF];   // h, e4m3 (pads 0)
__device__ __align__(16) char    g_uq[VP * KPF];      // emb_u * 0.5, e4m3
__device__ float     g_negsum[BATCH];
__device__ float     g_pos[BATCH];
__device__ unsigned  g_tflag[NT];    // per-tile release flag (== epoch+1 when ready)
__device__ unsigned  g_hcnt[16];     // per-m h-producer arrival counter
__device__ unsigned  g_done;
__device__ unsigned  g_epoch;

__device__ __forceinline__ uint32_t s2u(const void* p) {
    uint32_t a;
    asm("{ .reg .u64 t; cvta.to.shared.u64 t, %1; cvt.u32.u64 %0, t; }" : "=r"(a) : "l"(p));
    return a;
}
__device__ __forceinline__ float tanh_approx(float x) {
    float y;
    asm("tanh.approx.f32 %0, %1;" : "=f"(y) : "f"(x));
    return y;
}
__device__ __forceinline__ void cpa16(uint32_t dst, const void* src) {
    asm volatile("cp.async.cg.shared.global [%0], [%1], 16;" :: "r"(dst), "l"(src));
}
__device__ __forceinline__ void ldsm4(uint32_t& r0, uint32_t& r1, uint32_t& r2,
                                      uint32_t& r3, uint32_t addr) {
    asm volatile("ldmatrix.sync.aligned.m8n8.x4.shared.b16 {%0,%1,%2,%3}, [%4];"
                 : "=r"(r0), "=r"(r1), "=r"(r2), "=r"(r3) : "r"(addr));
}
__device__ __forceinline__ uint16_t fp8x2(float a, float b) {   // low byte = a
    uint16_t r;
    asm("cvt.rn.satfinite.e4m3x2.f32 %0, %1, %2;" : "=h"(r) : "f"(b), "f"(a));
    return r;
}
__device__ __forceinline__ unsigned ldacq(const unsigned* p) {
    unsigned v;
    asm volatile("ld.acquire.gpu.b32 %0, [%1];" : "=r"(v) : "l"(p) : "memory");
    return v;
}

// ---------------------------------------------------------------------------
// Persistent fused kernel (R13 structure, fp8 e4m3 tiles):
//  1. each CTA converts its OWNED B tiles (emb_u*0.5 -> e4m3), flag per tile
//  2. each CTA produces ~5 h rows of its m-block (+pos, negsum=0); per-m gate
//  3. gemm mainloop: 4 x m16n8k32 e4m3 mma -> f32 + tanh-sum epilogue
//  4. done-counter tail: last CTA reduces loss, writes out, bumps epoch
// ---------------------------------------------------------------------------
__global__ void __launch_bounds__(256, 3) k_fused(const int* __restrict__ x,
                                                  const int* __restrict__ y,
                                                  const float* __restrict__ emb_v,
                                                  const float* __restrict__ emb_u,
                                                  float* __restrict__ out) {
    extern __shared__ __align__(16) char smem[];
    __shared__ int sfin;
    uint32_t sbase = s2u(smem);
    int t = threadIdx.x, w = t >> 5, lane = t & 31;
    int g = lane >> 2, tig = lane & 3;
    int s = blockIdx.x, m = blockIdx.y;
    int mbase = m * BM;
    unsigned E = *(volatile unsigned*)&g_epoch;

    // ---- 1. Convert owned B tiles (emb_u * 0.5 -> e4m3, 128B rows) --------
    for (int q = m; q < 30; q += 16) {
        int j = s + 27 * q;
        if (j < NT) {
#pragma unroll
            for (int i = 0; i < 4; i++) {
                int unit = t + 256 * i;        // 64*16 = 1024 uint2 units/tile
                int row = unit >> 4, c = unit & 15;
                int v = j * 64 + row, k8 = c * 8;
                uint2 o2 = {0u, 0u};
                if (v < VOCAB) {
                    const float* rp = emb_u + (size_t)v * EMB;
                    if (k8 + 8 <= EMB) {
                        float4 fa = *(const float4*)(rp + k8);
                        float4 fb = *(const float4*)(rp + k8 + 4);
                        o2.x = (uint32_t)fp8x2(0.5f * fa.x, 0.5f * fa.y)
                             | ((uint32_t)fp8x2(0.5f * fa.z, 0.5f * fa.w) << 16);
                        o2.y = (uint32_t)fp8x2(0.5f * fb.x, 0.5f * fb.y)
                             | ((uint32_t)fp8x2(0.5f * fb.z, 0.5f * fb.w) << 16);
                    } else if (k8 < EMB) {     // k8 == 96: last 4 real cols
                        float4 fa = *(const float4*)(rp + k8);
                        o2.x = (uint32_t)fp8x2(0.5f * fa.x, 0.5f * fa.y)
                             | ((uint32_t)fp8x2(0.5f * fa.z, 0.5f * fa.w) << 16);
                    }
                }
                ((uint2*)g_uq)[(size_t)v * 16 + c] = o2;
            }
            __threadfence();
            __syncthreads();
            if (t == 0) atomicExch(&g_tflag[j], E + 1u);
        }
    }

    // ---- 2. Produce h rows [mbase+lo, mbase+hi) (one warp per row) --------
    int lo = (s * BM) / NSLICE, hi = ((s + 1) * BM) / NSLICE;
    if (w < hi - lo) {
        int b = mbase + lo + w;
        int cx[CTX];
#pragma unroll
        for (int c = 0; c < CTX; c++) cx[c] = x[b * CTX + c];
        const float* uy = emb_u + (size_t)y[b] * EMB;
        float pacc = 0.0f;
        uint32_t pk = 0;
#pragma unroll
        for (int pp = 0; pp < 4; pp++) {       // lane covers cols 4*lane..+3
            int col = 4 * lane + pp;
            float v = 0.0f;
            if (col < EMB) {
#pragma unroll
                for (int i = 0; i < CTX; i++) v += emb_v[(size_t)cx[i] * EMB + col];
                v *= 0.1f;
                pacc += v * uy[col];
            }
            pk |= ((uint32_t)fp8x2(v, 0.0f) & 0xFFu) << (8 * pp);
        }
#pragma unroll
        for (int o = 16; o; o >>= 1) pacc += __shfl_xor_sync(0xffffffffu, pacc, o);
        ((uint32_t*)(g_hq + (size_t)b * KPF))[lane] = pk;
        if (lane == 0) {
            float d = pacc;
            float ls = (d >= 0.0f) ? -log1pf(expf(-d)) : d - log1pf(expf(d));
            g_pos[b] = -ls;
            g_negsum[b] = 0.0f;
        }
    }
    __threadfence();
    __syncthreads();
    if (t == 0) {
        atomicAdd(&g_hcnt[m], 1u);
        unsigned tgt = (unsigned)NSLICE * (E + 1u);
        while (ldacq(&g_hcnt[m]) < tgt) __nanosleep(100);
    }
    __syncthreads();

    // ---- 3. GEMM mainloop --------------------------------------------------
    int t0 = (s * NT) / NSLICE;
    int t1 = ((s + 1) * NT) / NSLICE;
    int arow0 = (w >> 1) * 32;
    int brow0 = (w & 1) * 32;
    uint32_t aoff0 = sbase + (arow0 + (lane & 15)) * STRB + (lane >> 4) * 16;
    uint32_t boff0 = (brow0 + ((lane >> 4) << 3) + (lane & 7)) * STRB
                   + ((lane >> 3) & 1) * 16;

    const uint4* gA = (const uint4*)(g_hq + (size_t)mbase * KPF);
#pragma unroll
    for (int i = 0; i < 4; i++) {
        int idx = t + i * 256;               // 128*8 = 1024 chunks
        int r = idx >> 3, c = idx & 7;
        *(uint4*)(smem + r * STRB + c * 16) = gA[idx];
    }
    while (ldacq(&g_tflag[t0]) < E + 1u) __nanosleep(100);
    {
        const char* gB = g_uq + (size_t)t0 * BN * KPF;
        uint32_t sb = sbase + ABYTES;
#pragma unroll
        for (int i = 0; i < 2; i++) {
            int idx = t + i * 256;           // 64*8 = 512 chunks
            int r = idx >> 3, c = idx & 7;
            cpa16(sb + r * STRB + c * 16, gB + idx * 16);
        }
        asm volatile("cp.async.commit_group;" ::: "memory");
    }

    float rs[4] = {0.0f, 0.0f, 0.0f, 0.0f};

    for (int j = t0; j < t1; j++) {
        int par = (j - t0) & 1;
        asm volatile("cp.async.wait_group 0;" ::: "memory");
        __syncthreads();
        if (j + 1 < t1) {
            while (ldacq(&g_tflag[j + 1]) < E + 1u) __nanosleep(100);
            const char* gB = g_uq + (size_t)(j + 1) * BN * KPF;
            uint32_t sb = sbase + ABYTES + (par ^ 1) * BBYTES;
#pragma unroll
            for (int i = 0; i < 2; i++) {
                int idx = t + i * 256;
                int r = idx >> 3, c = idx & 7;
                cpa16(sb + r * STRB + c * 16, gB + idx * 16);
            }
            asm volatile("cp.async.commit_group;" ::: "memory");
        }

        uint32_t bbuf = sbase + ABYTES + par * BBYTES + boff0;
        float acc[2][4][4];
#pragma unroll
        for (int im = 0; im < 2; im++)
#pragma unroll
            for (int in = 0; in < 4; in++)
#pragma unroll
                for (int q = 0; q < 4; q++) acc[im][in][q] = 0.0f;

#pragma unroll
        for (int ks = 0; ks < 4; ks++) {
            int kb = ks * 32;                // 32 fp8 per k32 step
            uint32_t a[2][4], b[4][2];
#pragma unroll
            for (int im = 0; im < 2; im++)
                ldsm4(a[im][0], a[im][1], a[im][2], a[im][3],
                      aoff0 + im * 16 * STRB + kb);
#pragma unroll
            for (int jn = 0; jn < 2; jn++)
                ldsm4(b[2 * jn][0], b[2 * jn][1], b[2 * jn + 1][0], b[2 * jn + 1][1],
                      bbuf + jn * 16 * STRB + kb);
#pragma unroll
            for (int im = 0; im < 2; im++)
#pragma unroll
                for (int in = 0; in < 4; in++)
                    asm volatile(
                        "mma.sync.aligned.m16n8k32.row.col.f32.e4m3.e4m3.f32 "
                        "{%0,%1,%2,%3}, {%4,%5,%6,%7}, {%8,%9}, {%0,%1,%2,%3};"
                        : "+f"(acc[im][in][0]), "+f"(acc[im][in][1]),
                          "+f"(acc[im][in][2]), "+f"(acc[im][in][3])
                        : "r"(a[im][0]), "r"(a[im][1]),
                          "r"(a[im][2]), "r"(a[im][3]),
                          "r"(b[in][0]), "r"(b[in][1]));
        }

        // Epilogue: acc already = score/2; sum tanh only (pads give exact 0)
#pragma unroll
        for (int im = 0; im < 2; im++)
#pragma unroll
            for (int in = 0; in < 4; in++)
#pragma unroll
                for (int q = 0; q < 4; q++)
                    rs[im * 2 + (q >> 1)] += tanh_approx(acc[im][in][q]);
    }

#pragma unroll
    for (int i = 0; i < 4; i++) {
        rs[i] += __shfl_xor_sync(0xffffffff, rs[i], 1);
        rs[i] += __shfl_xor_sync(0xffffffff, rs[i], 2);
    }
    if (tig == 0) {
#pragma unroll
        for (int im = 0; im < 2; im++)
#pragma unroll
            for (int h = 0; h < 2; h++) {
                int row = mbase + arow0 + im * 16 + h * 8 + g;
                atomicAdd(&g_negsum[row], rs[im * 2 + h]);
            }
    }

    // ---- 4. Tail: last CTA reduces ----------------------------------------
    __threadfence();
    __syncthreads();
    if (t == 0) {
        unsigned old = atomicAdd(&g_done, 1u);
        sfin = (((old + 1u) % (unsigned)NCTA) == 0u);
    }
    __syncthreads();
    if (sfin) {
        float* sr = (float*)smem;
        float v = 0.0f;
        for (int i = t; i < BATCH; i += 256)
            v += __ldcg(&g_pos[i])
               + logf(0.5f * (float)VOCAB - 0.5f * __ldcg(&g_negsum[i]));
        sr[t] = v;
        __syncthreads();
        for (int o = 128; o; o >>= 1) {
            if (t < o) sr[t] += sr[t + o];
            __syncthreads();
        }
        if (t == 0) {
            out[0] = sr[0] / (float)BATCH;
            *(volatile unsigned*)&g_epoch = E + 1u;
        }
    }
}

// ---------------------------------------------------------------------------
extern "C" void kernel_launch(void* const* d_in, const int* in_sizes, int n_in,
                              void* d_out, int out_size) {
    const int*   x     = (const int*)d_in[0];
    const int*   y     = (const int*)d_in[1];
    const float* emb_v = (const float*)d_in[2];
    const float* emb_u = (const float*)d_in[3];

    cudaFuncSetAttribute(k_fused, cudaFuncAttributeMaxDynamicSharedMemorySize, SMEM_TOTAL);
    dim3 grid(NSLICE, BATCH / BM);  // 27 x 16 = 432 CTAs, all co-resident @3/SM
    k_fused<<<grid, 256, SMEM_TOTAL>>>(x, y, emb_v, emb_u, (float*)d_out);
}

// round 17
// speedup vs baseline: 1.0130x; 1.0130x over previous
#include <cuda_runtime.h>
#include <cuda_fp8.h>
#include <cstdint>

#define BATCH 2048
#define VOCAB 50000
#define EMB   100
#define CTX   10
#define KPF   128          // K padded to 128 fp8 (4 x k32 mma steps)
#define VP    50176        // 784 * 64
#define NT    784          // number of 64-row B tiles
#define BM    128
#define BN    64
#define NSLICE 27
#define NCTA  (NSLICE * 16)   // 432 CTAs, all co-resident at 3 CTAs/SM
#define STRB   144            // smem row stride bytes (128B data + 16 pad)
#define ABYTES (BM * STRB) // 18432
#define BBYTES (BN * STRB) // 9216
#define SMEM_TOTAL (ABYTES + 2 * BBYTES)  // 36864

// Scratch (device globals, zero-init at module load)
__device__ __align__(16) char    g_hq[BATCH * KPF];   // h, e4m3 (pads 0)
__device__ __align__(16) char    g_uq[VP * KPF];      // emb_u * 0.5, e4m3
__device__ float     g_negsum[BATCH];
__device__ float     g_pos[BATCH];
__device__ unsigned  g_tflag[NT];    // per-tile release flag (== epoch+1 when ready)
__device__ unsigned  g_hcnt[16];     // per-m h-producer arrival counter
__device__ unsigned  g_done;
__device__ unsigned  g_epoch;

__device__ __forceinline__ uint32_t s2u(const void* p) {
    uint32_t a;
    asm("{ .reg .u64 t; cvta.to.shared.u64 t, %1; cvt.u32.u64 %0, t; }" : "=r"(a) : "l"(p));
    return a;
}
__device__ __forceinline__ float tanh_approx(float x) {
    float y;
    asm("tanh.approx.f32 %0, %1;" : "=f"(y) : "f"(x));
    return y;
}
__device__ __forceinline__ void cpa16(uint32_t dst, const void* src) {
    asm volatile("cp.async.cg.shared.global [%0], [%1], 16;" :: "r"(dst), "l"(src));
}
__device__ __forceinline__ void ldsm4(uint32_t& r0, uint32_t& r1, uint32_t& r2,
                                      uint32_t& r3, uint32_t addr) {
    asm volatile("ldmatrix.sync.aligned.m8n8.x4.shared.b16 {%0,%1,%2,%3}, [%4];"
                 : "=r"(r0), "=r"(r1), "=r"(r2), "=r"(r3) : "r"(addr));
}
__device__ __forceinline__ uint16_t fp8x2(float a, float b) {   // low byte = a
    uint16_t r;
    asm("cvt.rn.satfinite.e4m3x2.f32 %0, %1, %2;" : "=h"(r) : "f"(b), "f"(a));
    return r;
}
__device__ __forceinline__ unsigned ldacq(const unsigned* p) {
    unsigned v;
    asm volatile("ld.acquire.gpu.b32 %0, [%1];" : "=r"(v) : "l"(p) : "memory");
    return v;
}

// ---------------------------------------------------------------------------
// Persistent fused kernel: R13 structure (t0-only spins + barrier broadcast),
// fp8 e4m3 tiles (43% less smem fragment traffic than bf16):
//  1. each CTA converts its OWNED B tiles (emb_u*0.5 -> e4m3), flag per tile
//  2. each CTA produces ~5 h rows of its m-block (+pos, negsum=0); per-m gate
//  3. gemm mainloop: 4 x m16n8k32 e4m3 mma -> f32 + tanh-sum epilogue
//  4. done-counter tail: last CTA reduces loss, writes out, bumps epoch
// ---------------------------------------------------------------------------
__global__ void __launch_bounds__(256, 3) k_fused(const int* __restrict__ x,
                                                  const int* __restrict__ y,
                                                  const float* __restrict__ emb_v,
                                                  const float* __restrict__ emb_u,
                                                  float* __restrict__ out) {
    extern __shared__ __align__(16) char smem[];
    __shared__ int sfin;
    uint32_t sbase = s2u(smem);
    int t = threadIdx.x, w = t >> 5, lane = t & 31;
    int g = lane >> 2, tig = lane & 3;
    int s = blockIdx.x, m = blockIdx.y;
    int mbase = m * BM;
    unsigned E = *(volatile unsigned*)&g_epoch;

    // ---- 1. Convert owned B tiles (emb_u * 0.5 -> e4m3, 128B rows) --------
    for (int q = m; q < 30; q += 16) {
        int j = s + 27 * q;
        if (j < NT) {
#pragma unroll
            for (int i = 0; i < 4; i++) {
                int unit = t + 256 * i;        // 64*16 = 1024 uint2 units/tile
                int row = unit >> 4, c = unit & 15;
                int v = j * 64 + row, k8 = c * 8;
                uint2 o2 = {0u, 0u};
                if (v < VOCAB) {
                    const float* rp = emb_u + (size_t)v * EMB;
                    if (k8 + 8 <= EMB) {
                        float4 fa = *(const float4*)(rp + k8);
                        float4 fb = *(const float4*)(rp + k8 + 4);
                        o2.x = (uint32_t)fp8x2(0.5f * fa.x, 0.5f * fa.y)
                             | ((uint32_t)fp8x2(0.5f * fa.z, 0.5f * fa.w) << 16);
                        o2.y = (uint32_t)fp8x2(0.5f * fb.x, 0.5f * fb.y)
                             | ((uint32_t)fp8x2(0.5f * fb.z, 0.5f * fb.w) << 16);
                    } else if (k8 < EMB) {     // k8 == 96: last 4 real cols
                        float4 fa = *(const float4*)(rp + k8);
                        o2.x = (uint32_t)fp8x2(0.5f * fa.x, 0.5f * fa.y)
                             | ((uint32_t)fp8x2(0.5f * fa.z, 0.5f * fa.w) << 16);
                    }
                }
                ((uint2*)g_uq)[(size_t)v * 16 + c] = o2;
            }
            __threadfence();
            __syncthreads();
            if (t == 0) atomicExch(&g_tflag[j], E + 1u);
        }
    }

    // ---- 2. Produce h rows [mbase+lo, mbase+hi) (one warp per row) --------
    int lo = (s * BM) / NSLICE, hi = ((s + 1) * BM) / NSLICE;
    if (w < hi - lo) {
        int b = mbase + lo + w;
        int cx[CTX];
#pragma unroll
        for (int c = 0; c < CTX; c++) cx[c] = x[b * CTX + c];
        const float* uy = emb_u + (size_t)y[b] * EMB;
        float pacc = 0.0f;
        uint32_t pk = 0;
#pragma unroll
        for (int pp = 0; pp < 4; pp++) {       // lane covers cols 4*lane..+3
            int col = 4 * lane + pp;
            float v = 0.0f;
            if (col < EMB) {
#pragma unroll
                for (int i = 0; i < CTX; i++) v += emb_v[(size_t)cx[i] * EMB + col];
                v *= 0.1f;
                pacc += v * uy[col];
            }
            pk |= ((uint32_t)fp8x2(v, 0.0f) & 0xFFu) << (8 * pp);
        }
#pragma unroll
        for (int o = 16; o; o >>= 1) pacc += __shfl_xor_sync(0xffffffffu, pacc, o);
        ((uint32_t*)(g_hq + (size_t)b * KPF))[lane] = pk;
        if (lane == 0) {
            float d = pacc;
            float ls = (d >= 0.0f) ? -log1pf(expf(-d)) : d - log1pf(expf(d));
            g_pos[b] = -ls;
            g_negsum[b] = 0.0f;
        }
    }
    __threadfence();
    __syncthreads();
    if (t == 0) {
        atomicAdd(&g_hcnt[m], 1u);
        unsigned tgt = (unsigned)NSLICE * (E + 1u);
        while (ldacq(&g_hcnt[m]) < tgt) __nanosleep(100);
    }
    __syncthreads();

    // ---- 3. GEMM mainloop --------------------------------------------------
    int t0 = (s * NT) / NSLICE;
    int t1 = ((s + 1) * NT) / NSLICE;
    int arow0 = (w >> 1) * 32;
    int brow0 = (w & 1) * 32;
    uint32_t aoff0 = sbase + (arow0 + (lane & 15)) * STRB + (lane >> 4) * 16;
    uint32_t boff0 = (brow0 + ((lane >> 4) << 3) + (lane & 7)) * STRB
                   + ((lane >> 3) & 1) * 16;

    const uint4* gA = (const uint4*)(g_hq + (size_t)mbase * KPF);
#pragma unroll
    for (int i = 0; i < 4; i++) {
        int idx = t + i * 256;               // 128*8 = 1024 chunks
        int r = idx >> 3, c = idx & 7;
        *(uint4*)(smem + r * STRB + c * 16) = gA[idx];
    }
    if (t == 0) { while (ldacq(&g_tflag[t0]) < E + 1u) __nanosleep(100); }
    __syncthreads();
    {
        const char* gB = g_uq + (size_t)t0 * BN * KPF;
        uint32_t sb = sbase + ABYTES;
#pragma unroll
        for (int i = 0; i < 2; i++) {
            int idx = t + i * 256;           // 64*8 = 512 chunks
            int r = idx >> 3, c = idx & 7;
            cpa16(sb + r * STRB + c * 16, gB + idx * 16);
        }
        asm volatile("cp.async.commit_group;" ::: "memory");
    }

    float rs[4] = {0.0f, 0.0f, 0.0f, 0.0f};

    for (int j = t0; j < t1; j++) {
        int par = (j - t0) & 1;
        asm volatile("cp.async.wait_group 0;" ::: "memory");
        __syncthreads();
        if (j + 1 < t1) {
            if (t == 0) { while (ldacq(&g_tflag[j + 1]) < E + 1u) __nanosleep(100); }
            __syncthreads();
            const char* gB = g_uq + (size_t)(j + 1) * BN * KPF;
            uint32_t sb = sbase + ABYTES + (par ^ 1) * BBYTES;
#pragma unroll
            for (int i = 0; i < 2; i++) {
                int idx = t + i * 256;
                int r = idx >> 3, c = idx & 7;
                cpa16(sb + r * STRB + c * 16, gB + idx * 16);
            }
            asm volatile("cp.async.commit_group;" ::: "memory");
        }

        uint32_t bbuf = sbase + ABYTES + par * BBYTES + boff0;
        float acc[2][4][4];
#pragma unroll
        for (int im = 0; im < 2; im++)
#pragma unroll
            for (int in = 0; in < 4; in++)
#pragma unroll
                for (int q = 0; q < 4; q++) acc[im][in][q] = 0.0f;

#pragma unroll
        for (int ks = 0; ks < 4; ks++) {
            int kb = ks * 32;                // 32 fp8 per k32 step
            uint32_t a[2][4], b[4][2];
#pragma unroll
            for (int im = 0; im < 2; im++)
                ldsm4(a[im][0], a[im][1], a[im][2], a[im][3],
                      aoff0 + im * 16 * STRB + kb);
#pragma unroll
            for (int jn = 0; jn < 2; jn++)
                ldsm4(b[2 * jn][0], b[2 * jn][1], b[2 * jn + 1][0], b[2 * jn + 1][1],
                      bbuf + jn * 16 * STRB + kb);
#pragma unroll
            for (int im = 0; im < 2; im++)
#pragma unroll
                for (int in = 0; in < 4; in++)
                    asm volatile(
                        "mma.sync.aligned.m16n8k32.row.col.f32.e4m3.e4m3.f32 "
                        "{%0,%1,%2,%3}, {%4,%5,%6,%7}, {%8,%9}, {%0,%1,%2,%3};"
                        : "+f"(acc[im][in][0]), "+f"(acc[im][in][1]),
                          "+f"(acc[im][in][2]), "+f"(acc[im][in][3])
                        : "r"(a[im][0]), "r"(a[im][1]),
                          "r"(a[im][2]), "r"(a[im][3]),
                          "r"(b[in][0]), "r"(b[in][1]));
        }

        // Epilogue: acc already = score/2; sum tanh only (pads give exact 0)
#pragma unroll
        for (int im = 0; im < 2; im++)
#pragma unroll
            for (int in = 0; in < 4; in++)
#pragma unroll
                for (int q = 0; q < 4; q++)
                    rs[im * 2 + (q >> 1)] += tanh_approx(acc[im][in][q]);
    }

#pragma unroll
    for (int i = 0; i < 4; i++) {
        rs[i] += __shfl_xor_sync(0xffffffff, rs[i], 1);
        rs[i] += __shfl_xor_sync(0xffffffff, rs[i], 2);
    }
    if (tig == 0) {
#pragma unroll
        for (int im = 0; im < 2; im++)
#pragma unroll
            for (int h = 0; h < 2; h++) {
                int row = mbase + arow0 + im * 16 + h * 8 + g;
                atomicAdd(&g_negsum[row], rs[im * 2 + h]);
            }
    }

    // ---- 4. Tail: last CTA reduces ----------------------------------------
    __threadfence();
    __syncthreads();
    if (t == 0) {
        unsigned old = atomicAdd(&g_done, 1u);
        sfin = (((old + 1u) % (unsigned)NCTA) == 0u);
    }
    __syncthreads();
    if (sfin) {
        float* sr = (float*)smem;
        float v = 0.0f;
        for (int i = t; i < BATCH; i += 256)
            v += __ldcg(&g_pos[i])
               + logf(0.5f * (float)VOCAB - 0.5f * __ldcg(&g_negsum[i]));
        sr[t] = v;
        __syncthreads();
        for (int o = 128; o; o >>= 1) {
            if (t < o) sr[t] += sr[t + o];
            __syncthreads();
        }
        if (t == 0) {
            out[0] = sr[0] / (float)BATCH;
            *(volatile unsigned*)&g_epoch = E + 1u;
        }
    }
}

// ---------------------------------------------------------------------------
extern "C" void kernel_launch(void* const* d_in, const int* in_sizes, int n_in,
                              void* d_out, int out_size) {
    const int*   x     = (const int*)d_in[0];
    const int*   y     = (const int*)d_in[1];
    const float* emb_v = (const float*)d_in[2];
    const float* emb_u = (const float*)d_in[3];

    cudaFuncSetAttribute(k_fused, cudaFuncAttributeMaxDynamicSharedMemorySize, SMEM_TOTAL);
    dim3 grid(NSLICE, BATCH / BM);  // 27 x 16 = 432 CTAs, all co-resident @3/SM
    k_fused<<<grid, 256, SMEM_TOTAL>>>(x, y, emb_v, emb_u, (float*)d_out);
}